// round 1
// baseline (speedup 1.0000x reference)
#include <cuda_runtime.h>
#include <math.h>

// Problem dims
#define Bn   128
#define Tn   20
#define Vn   12000
#define En   512
#define Hn   512
#define VISn 512
#define NVn  64

// ---------------- scratch (device globals; no runtime allocation) ----------------
__device__ float g_fT[Bn * 49 * VISn];            // transposed conv features (B*49, 512)
__device__ float g_fv[Bn * 49 * VISn];            // att_fc output (pre-normalize)
__device__ float g_features_all[Bn * 64 * VISn];  // [B,64,512] normalized fv ++ eng tokens
__device__ float g_we[Bn * Tn * En];              // word embeddings [B,T,512]
__device__ float g_att_fea[Bn * 64 * VISn];       // features_all @ att_vw_w.T
__device__ float g_att_h[Bn * Tn * VISn];         // we @ att_hw_w.T (all T rows; t<19 used)
__device__ float g_feas_seq[Bn * Tn * VISn];      // [B,T,512] visual context per step
__device__ float g_xg[Bn * Tn * 4 * Hn];          // precomputed input gates [B,T,2048]
__device__ float g_c[Bn * Hn];                    // LSTM cell state
__device__ float g_h0[Bn * Hn];                   // zero h for step 0
__device__ float g_hs[Bn * Tn * Hn];              // all hidden states [B,T,512]
__device__ float g_bias2[4 * Hn];                 // b_ih + b_hh

// ---------------- generic fp32 GEMM: C[M,N] = A[M,K] @ B[N,K]^T ----------------
// mode 0: C = acc (+bias)     mode 1: C += acc (accumulate)
// mode 2: C = (lengths[row/T] >= row%T) ? acc+bias : 0   (masked fc epilogue)
__global__ __launch_bounds__(256)
void sgemm_nt(const float* __restrict__ A, int lda,
              const float* __restrict__ Bw, int ldb,
              float* __restrict__ C, int ldc,
              const float* __restrict__ bias,
              int M, int N, int K,
              int mode, const int* __restrict__ lengths)
{
    __shared__ float As[16][64];
    __shared__ float Bs[16][64];

    const int tid = threadIdx.x;        // 256 threads
    const int tx  = tid & 15;           // n-dir
    const int ty  = tid >> 4;           // m-dir
    const int m0  = blockIdx.y * 64;
    const int n0  = blockIdx.x * 64;

    const int lrow  = tid >> 2;         // 0..63 (tile row this thread loads)
    const int lcol4 = (tid & 3) * 4;    // k offset (float4)

    const bool avalid = (m0 + lrow) < M;
    const bool bvalid = (n0 + lrow) < N;
    const float* Ap = A  + (long)(m0 + lrow) * lda + lcol4;
    const float* Bp = Bw + (long)(n0 + lrow) * ldb + lcol4;

    float acc[4][4] = {};

    for (int k0 = 0; k0 < K; k0 += 16) {
        float4 av = avalid ? *(const float4*)(Ap + k0) : make_float4(0.f, 0.f, 0.f, 0.f);
        float4 bv = bvalid ? *(const float4*)(Bp + k0) : make_float4(0.f, 0.f, 0.f, 0.f);
        __syncthreads();
        As[lcol4 + 0][lrow] = av.x; As[lcol4 + 1][lrow] = av.y;
        As[lcol4 + 2][lrow] = av.z; As[lcol4 + 3][lrow] = av.w;
        Bs[lcol4 + 0][lrow] = bv.x; Bs[lcol4 + 1][lrow] = bv.y;
        Bs[lcol4 + 2][lrow] = bv.z; Bs[lcol4 + 3][lrow] = bv.w;
        __syncthreads();
        #pragma unroll
        for (int kk = 0; kk < 16; kk++) {
            float a[4], b[4];
            #pragma unroll
            for (int i = 0; i < 4; i++) a[i] = As[kk][ty * 4 + i];
            #pragma unroll
            for (int j = 0; j < 4; j++) b[j] = Bs[kk][tx * 4 + j];
            #pragma unroll
            for (int i = 0; i < 4; i++)
                #pragma unroll
                for (int j = 0; j < 4; j++)
                    acc[i][j] += a[i] * b[j];
        }
    }

    #pragma unroll
    for (int i = 0; i < 4; i++) {
        int row = m0 + ty * 4 + i;
        if (row >= M) continue;
        #pragma unroll
        for (int j = 0; j < 4; j++) {
            int col = n0 + tx * 4 + j;
            if (col >= N) continue;
            float v = acc[i][j];
            long off = (long)row * ldc + col;
            if (mode == 1) {
                C[off] += v;
            } else {
                if (bias) v += bias[col];
                if (mode == 2) {
                    int bb = row / Tn, tt = row % Tn;
                    if (lengths[bb] < tt) v = 0.f;
                }
                C[off] = v;
            }
        }
    }
}

// ---------------- small prep kernels ----------------
__global__ void k_init_state() {
    int i = blockIdx.x * blockDim.x + threadIdx.x;
    if (i < Bn * Hn) { g_c[i] = 0.f; g_h0[i] = 0.f; }
}

__global__ void k_bias2(const float* __restrict__ b_ih, const float* __restrict__ b_hh) {
    int i = blockIdx.x * blockDim.x + threadIdx.x;
    if (i < 4 * Hn) g_bias2[i] = b_ih[i] + b_hh[i];
}

// features (B,512,1,7,7) -> g_fT[(b*49+p)*512 + v]
__global__ void k_transpose_f(const float* __restrict__ features) {
    int bp = blockIdx.x;                 // b*49+p
    int b = bp / 49, p = bp % 49;
    int v = threadIdx.x;                 // 512
    g_fT[(long)bp * 512 + v] = features[((long)b * 512 + v) * 49 + p];
}

// L2-normalize fv rows, write into features_all token slots 0..48
__global__ void k_normalize() {
    int row = blockIdx.x;                // b*49+p
    int b = row / 49, p = row % 49;
    const float* x = g_fv + (long)row * 512;
    __shared__ float red[8];
    int tid = threadIdx.x, lane = tid & 31, wid = tid >> 5;
    float s = 0.f;
    for (int v = tid; v < 512; v += 256) { float t = x[v]; s += t * t; }
    #pragma unroll
    for (int o = 16; o; o >>= 1) s += __shfl_xor_sync(0xffffffffu, s, o);
    if (lane == 0) red[wid] = s;
    __syncthreads();
    if (tid == 0) {
        float sum = 0.f;
        #pragma unroll
        for (int w = 0; w < 8; w++) sum += red[w];
        red[0] = 1.f / fmaxf(sqrtf(sum), 1e-12f);
    }
    __syncthreads();
    float inv = red[0];
    float* o = g_features_all + ((long)b * 64 + p) * 512;
    for (int v = tid; v < 512; v += 256) o[v] = x[v] * inv;
}

// eng_embedding (B,15,512) -> features_all token slots 49..63
__global__ void k_copy_eng(const float* __restrict__ eng) {
    int bj = blockIdx.x;                 // b*15+j
    int b = bj / 15, j = bj % 15;
    int v = threadIdx.x;
    g_features_all[((long)b * 64 + 49 + j) * 512 + v] = eng[(long)bj * 512 + v];
}

// word embedding gather
__global__ void k_embed(const int* __restrict__ captions, const float* __restrict__ embed_w) {
    int r = blockIdx.x;                  // b*T+t
    int idx = captions[r];
    g_we[(long)r * 512 + threadIdx.x] = embed_w[(long)idx * 512 + threadIdx.x];
}

// ---------------- fused attention: scores + softmax + context ----------------
// block (t, b): t in 0..18. 512 threads. Writes feas_seq[b, t+1, :].
__global__ __launch_bounds__(512)
void k_attention(const float* __restrict__ att_bias, const float* __restrict__ att_w) {
    int t = blockIdx.x, b = blockIdx.y;
    __shared__ float hh[512], ws[512], sb[64], sout[64];
    int tid = threadIdx.x, lane = tid & 31, wid = tid >> 5;

    hh[tid] = g_att_h[((long)b * Tn + t) * 512 + tid];
    ws[tid] = att_w[tid];
    if (tid < 64) sb[tid] = att_bias[tid];
    __syncthreads();

    // warp-per-token scores: sout[n] = sum_v relu(fea + hh + bias[n]) * ws[v]
    for (int n = wid; n < 64; n += 16) {
        const float* fea = g_att_fea + ((long)b * 64 + n) * 512;
        float bn = sb[n], s = 0.f;
        for (int v = lane; v < 512; v += 32)
            s += fmaxf(fea[v] + hh[v] + bn, 0.f) * ws[v];
        #pragma unroll
        for (int o = 16; o; o >>= 1) s += __shfl_xor_sync(0xffffffffu, s, o);
        if (lane == 0) sout[n] = s;
    }
    __syncthreads();

    // softmax over 64 tokens (cheap: single thread)
    if (tid == 0) {
        float mx = sout[0];
        for (int n = 1; n < 64; n++) mx = fmaxf(mx, sout[n]);
        float sum = 0.f;
        for (int n = 0; n < 64; n++) { float e = __expf(sout[n] - mx); sout[n] = e; sum += e; }
        float inv = 1.f / sum;
        for (int n = 0; n < 64; n++) sout[n] *= inv;
    }
    __syncthreads();

    // context: ctx[v] = sum_n alpha[n] * features_all[b,n,v]
    float acc = 0.f;
    const float* fa = g_features_all + (long)b * 64 * 512 + tid;
    #pragma unroll 8
    for (int n = 0; n < 64; n++) acc += sout[n] * fa[(long)n * 512];
    g_feas_seq[((long)b * Tn + (t + 1)) * 512 + tid] = acc;
}

// ---------------- fused LSTM step: gates = xg_t + h@w_hh.T; pointwise; state ----------------
// grid: (Hn/16 = 32, Bn/32 = 4); 256 threads.
__global__ __launch_bounds__(256)
void k_lstm_step(const float* __restrict__ w_hh,
                 const float* __restrict__ hprev, int hstride, int t)
{
    __shared__ float Hs[16][32];
    __shared__ float Ws[16][64];
    __shared__ float Gs[32][65];

    int tid = threadIdx.x;
    int tx = tid & 15, ty = tid >> 4;
    int hc0 = blockIdx.x * 16;
    int b0  = blockIdx.y * 32;

    float acc[2][4] = {};

    for (int k0 = 0; k0 < Hn; k0 += 16) {
        __syncthreads();
        for (int i = tid; i < 32 * 16; i += 256) {
            int r = i >> 4, k = i & 15;
            Hs[k][r] = hprev[(long)(b0 + r) * hstride + k0 + k];
        }
        for (int i = tid; i < 64 * 16; i += 256) {
            int v = i >> 4, k = i & 15;
            int j = (v >> 4) * Hn + hc0 + (v & 15);     // gate-major virtual col
            Ws[k][v] = w_hh[(long)j * Hn + k0 + k];
        }
        __syncthreads();
        #pragma unroll
        for (int kk = 0; kk < 16; kk++) {
            float a0 = Hs[kk][ty * 2 + 0];
            float a1 = Hs[kk][ty * 2 + 1];
            float bb[4];
            #pragma unroll
            for (int j = 0; j < 4; j++) bb[j] = Ws[kk][tx * 4 + j];
            #pragma unroll
            for (int j = 0; j < 4; j++) { acc[0][j] += a0 * bb[j]; acc[1][j] += a1 * bb[j]; }
        }
    }

    // stage gates (+ precomputed xg) to smem in [row][gate*16+l] layout
    #pragma unroll
    for (int mi = 0; mi < 2; mi++) {
        int m = ty * 2 + mi;
        #pragma unroll
        for (int ni = 0; ni < 4; ni++) {
            int v = tx * 4 + ni;
            int j = (v >> 4) * Hn + hc0 + (v & 15);
            Gs[m][v] = acc[mi][ni] + g_xg[((long)(b0 + m) * Tn + t) * (4 * Hn) + j];
        }
    }
    __syncthreads();

    // pointwise: each of 512 (row,l) pairs handled; 256 threads x 2
    for (int p = tid; p < 32 * 16; p += 256) {
        int r = p >> 4, l = p & 15;
        int b = b0 + r, hcol = hc0 + l;
        float gi = Gs[r][l +  0];
        float gf = Gs[r][l + 16];
        float gg = Gs[r][l + 32];
        float go = Gs[r][l + 48];
        float co = g_c[(long)b * Hn + hcol];
        float si = 1.f / (1.f + __expf(-gi));
        float sf = 1.f / (1.f + __expf(-gf));
        float so = 1.f / (1.f + __expf(-go));
        float cn = sf * co + si * tanhf(gg);
        float hn = so * tanhf(cn);
        g_c[(long)b * Hn + hcol] = cn;
        g_hs[((long)b * Tn + t) * Hn + hcol] = hn;
    }
}

// ---------------- launch ----------------
static inline dim3 gemm_grid(int M, int N) { return dim3((N + 63) / 64, (M + 63) / 64); }

extern "C" void kernel_launch(void* const* d_in, const int* in_sizes, int n_in,
                              void* d_out, int out_size)
{
    const float* feature_0 = (const float*)d_in[0];
    const float* features  = (const float*)d_in[1];
    const float* eng       = (const float*)d_in[2];
    const int*   captions  = (const int*)  d_in[3];
    const int*   lengths   = (const int*)  d_in[4];
    const float* embed_w   = (const float*)d_in[5];
    const float* w_ih      = (const float*)d_in[6];
    const float* w_hh      = (const float*)d_in[7];
    const float* b_ih      = (const float*)d_in[8];
    const float* b_hh      = (const float*)d_in[9];
    const float* fc_w      = (const float*)d_in[10];
    const float* fc_b      = (const float*)d_in[11];
    const float* att_vw_w  = (const float*)d_in[12];
    const float* att_hw_w  = (const float*)d_in[13];
    const float* att_bias  = (const float*)d_in[14];
    const float* att_w_w   = (const float*)d_in[15];
    const float* att_fc_w  = (const float*)d_in[16];
    const float* att_fc_b  = (const float*)d_in[17];
    const float* img_w     = (const float*)d_in[18];
    const float* img_b     = (const float*)d_in[19];
    float* out = (float*)d_out;

    float* p_fT    = nullptr; cudaGetSymbolAddress((void**)&p_fT,    g_fT);
    float* p_fv    = nullptr; cudaGetSymbolAddress((void**)&p_fv,    g_fv);
    float* p_fall  = nullptr; cudaGetSymbolAddress((void**)&p_fall,  g_features_all);
    float* p_we    = nullptr; cudaGetSymbolAddress((void**)&p_we,    g_we);
    float* p_afea  = nullptr; cudaGetSymbolAddress((void**)&p_afea,  g_att_fea);
    float* p_ah    = nullptr; cudaGetSymbolAddress((void**)&p_ah,    g_att_h);
    float* p_fseq  = nullptr; cudaGetSymbolAddress((void**)&p_fseq,  g_feas_seq);
    float* p_xg    = nullptr; cudaGetSymbolAddress((void**)&p_xg,    g_xg);
    float* p_h0    = nullptr; cudaGetSymbolAddress((void**)&p_h0,    g_h0);
    float* p_hs    = nullptr; cudaGetSymbolAddress((void**)&p_hs,    g_hs);
    float* p_bias2 = nullptr; cudaGetSymbolAddress((void**)&p_bias2, g_bias2);

    // init / prep
    k_init_state<<<(Bn * Hn + 511) / 512, 512>>>();
    k_bias2<<<(4 * Hn + 255) / 256, 256>>>(b_ih, b_hh);
    k_transpose_f<<<Bn * 49, 512>>>(features);
    k_embed<<<Bn * Tn, 512>>>(captions, embed_w);
    k_copy_eng<<<Bn * 15, 512>>>(eng);

    // att_fc: fv = fT @ att_fc_w.T + b     (M=6272, N=512, K=512)
    sgemm_nt<<<gemm_grid(Bn * 49, 512), 256>>>(p_fT, 512, att_fc_w, 512,
        p_fv, 512, att_fc_b, Bn * 49, 512, 512, 0, nullptr);
    k_normalize<<<Bn * 49, 256>>>();

    // img: feas_seq[:,0,:] = feature_0 @ img_w.T + img_b   (M=128, N=512, K=2048)
    sgemm_nt<<<gemm_grid(Bn, 512), 256>>>(feature_0, 2048, img_w, 2048,
        p_fseq, Tn * VISn, img_b, Bn, 512, 2048, 0, nullptr);

    // att_fea = features_all @ att_vw_w.T   (M=8192, N=512, K=512)
    sgemm_nt<<<gemm_grid(Bn * 64, 512), 256>>>(p_fall, 512, att_vw_w, 512,
        p_afea, 512, nullptr, Bn * 64, 512, 512, 0, nullptr);

    // att_h = we @ att_hw_w.T   (M=2560, N=512, K=512; only t<19 rows used later)
    sgemm_nt<<<gemm_grid(Bn * Tn, 512), 256>>>(p_we, 512, att_hw_w, 512,
        p_ah, 512, nullptr, Bn * Tn, 512, 512, 0, nullptr);

    // fused attention -> feas_seq[:,1..19,:]
    k_attention<<<dim3(Tn - 1, Bn), 512>>>(att_bias, att_w_w);

    // xg = feas_seq @ w_ih[:, :512].T + (b_ih+b_hh)  ;  xg += we @ w_ih[:, 512:].T
    sgemm_nt<<<gemm_grid(Bn * Tn, 4 * Hn), 256>>>(p_fseq, 512, w_ih, 1024,
        p_xg, 4 * Hn, p_bias2, Bn * Tn, 4 * Hn, 512, 0, nullptr);
    sgemm_nt<<<gemm_grid(Bn * Tn, 4 * Hn), 256>>>(p_we, 512, w_ih + 512, 1024,
        p_xg, 4 * Hn, nullptr, Bn * Tn, 4 * Hn, 512, 1, nullptr);

    // LSTM recurrence: only h @ w_hh.T is serial
    for (int t = 0; t < Tn; t++) {
        const float* hprev = (t == 0) ? p_h0 : (p_hs + (long)(t - 1) * Hn);
        int hstride = (t == 0) ? Hn : Tn * Hn;
        k_lstm_step<<<dim3(Hn / 16, Bn / 32), 256>>>(w_hh, hprev, hstride, t);
    }

    // logits + mask: out = hs @ fc_w.T + fc_b, zeroed where lengths[b] < t
    sgemm_nt<<<gemm_grid(Bn * Tn, Vn), 256>>>(p_hs, 512, fc_w, 512,
        out, Vn, fc_b, Bn * Tn, Vn, 512, 2, lengths);
}